// round 15
// baseline (speedup 1.0000x reference)
#include <cuda_runtime.h>
#include <math.h>

static constexpr int BATCH = 64;
static constexpr int H  = 256;
static constexpr int W  = 256;
static constexpr int HW = H * W;          // 65536
static constexpr int HW4 = HW / 4;        // 16384 float4 groups per channel
static constexpr int NK = 68;
static constexpr int APPLY_UNITS = BATCH * HW4 / 256;  // 4096 units
static constexpr int APPLY_BLOCKS = 1184;              // 148 SMs x 8 resident

// Per-batch similarity transform: 9 floats sR (row-major [d][c]) + 3 floats t.
__device__ float g_params[BATCH * 12];

// ---------------------------------------------------------------------------
// Kernel 1: per-batch Umeyama estimation (64 blocks x 128 threads).
// (Latency-floor version; measured invariant across rewrites.)
// ---------------------------------------------------------------------------
__global__ void __launch_bounds__(128)
estimate_kernel(const float* __restrict__ Off,
                const float* __restrict__ Pos,
                const float* __restrict__ Mp,
                const int*   __restrict__ uv)
{
    const int b   = blockIdx.x;
    const int tid = threadIdx.x;

    __shared__ float mom[16][NK + 1];
    __shared__ float ssum[16];

    if (tid < NK) {
        const int h = __ldg(&uv[2 * tid + 0]);
        const int w = __ldg(&uv[2 * tid + 1]);
        const int base = b * 3 * HW + h * W + w;
        const int mb   = h * W + w;
        // offsetmap = (Offset*4 + mean) * REVERT, REVERT = [1,-1,1]
        const float s0 =  fmaf(Off[base         ], 4.0f, Mp[mb         ]);
        const float s1 = -fmaf(Off[base +    HW ], 4.0f, Mp[mb +    HW ]);
        const float s2 =  fmaf(Off[base + 2*HW  ], 4.0f, Mp[mb + 2*HW  ]);
        const float d0 = Pos[base];
        const float d1 = Pos[base + HW];
        const float d2 = Pos[base + 2 * HW];

        mom[0][tid]  = s0;       mom[1][tid]  = s1;       mom[2][tid]  = s2;
        mom[3][tid]  = d0;       mom[4][tid]  = d1;       mom[5][tid]  = d2;
        mom[6][tid]  = d0 * s0;  mom[7][tid]  = d0 * s1;  mom[8][tid]  = d0 * s2;
        mom[9][tid]  = d1 * s0;  mom[10][tid] = d1 * s1;  mom[11][tid] = d1 * s2;
        mom[12][tid] = d2 * s0;  mom[13][tid] = d2 * s1;  mom[14][tid] = d2 * s2;
        mom[15][tid] = s0 * s0 + s1 * s1 + s2 * s2;
    }
    __syncthreads();

    if (tid < 16) {
        float a0 = 0.f, a1 = 0.f, a2 = 0.f, a3 = 0.f;
        #pragma unroll
        for (int i = 0; i < 68; i += 4) {
            a0 += mom[tid][i + 0];
            a1 += mom[tid][i + 1];
            a2 += mom[tid][i + 2];
            a3 += mom[tid][i + 3];
        }
        ssum[tid] = ((a0 + a1) + (a2 + a3)) * (1.0f / NK);
    }
    __syncthreads();

    if (tid == 0) {
        const float mus0 = ssum[0], mus1 = ssum[1], mus2 = ssum[2];
        const float mud0 = ssum[3], mud1 = ssum[4], mud2 = ssum[5];

        float A[3][3];
        A[0][0] = ssum[6]  - mud0*mus0; A[0][1] = ssum[7]  - mud0*mus1; A[0][2] = ssum[8]  - mud0*mus2;
        A[1][0] = ssum[9]  - mud1*mus0; A[1][1] = ssum[10] - mud1*mus1; A[1][2] = ssum[11] - mud1*mus2;
        A[2][0] = ssum[12] - mud2*mus0; A[2][1] = ssum[13] - mud2*mus1; A[2][2] = ssum[14] - mud2*mus2;
        const float var_s = ssum[15] - (mus0*mus0 + mus1*mus1 + mus2*mus2);

        const float detA =
              A[0][0] * (A[1][1]*A[2][2] - A[1][2]*A[2][1])
            - A[0][1] * (A[1][0]*A[2][2] - A[1][2]*A[2][0])
            + A[0][2] * (A[1][0]*A[2][1] - A[1][1]*A[2][0]);

        float Bm[3][3], Vm[3][3] = {{1,0,0},{0,1,0},{0,0,1}};
        #pragma unroll
        for (int i = 0; i < 3; i++)
            #pragma unroll
            for (int j = 0; j < 3; j++) {
                float acc = 0.0f;
                #pragma unroll
                for (int k = 0; k < 3; k++) acc += A[k][i] * A[k][j];
                Bm[i][j] = acc;
            }

        const int PP[3] = {0, 0, 1}, QQ[3] = {1, 2, 2};
        #pragma unroll 1
        for (int sweep = 0; sweep < 4; sweep++) {
            #pragma unroll
            for (int r = 0; r < 3; r++) {
                const int p = PP[r], q = QQ[r];
                const float apq = Bm[p][q];
                if (fabsf(apq) < 1e-30f) continue;
                const float theta = (Bm[q][q] - Bm[p][p]) / (2.0f * apq);
                const float tt = ((theta >= 0.0f) ? 1.0f : -1.0f) /
                                 (fabsf(theta) + sqrtf(theta * theta + 1.0f));
                const float c = rsqrtf(tt * tt + 1.0f);
                const float s = tt * c;
                #pragma unroll
                for (int k = 0; k < 3; k++) {
                    const float bkp = Bm[k][p], bkq = Bm[k][q];
                    Bm[k][p] = c * bkp - s * bkq;
                    Bm[k][q] = s * bkp + c * bkq;
                }
                #pragma unroll
                for (int k = 0; k < 3; k++) {
                    const float bpk = Bm[p][k], bqk = Bm[q][k];
                    Bm[p][k] = c * bpk - s * bqk;
                    Bm[q][k] = s * bpk + c * bqk;
                }
                #pragma unroll
                for (int k = 0; k < 3; k++) {
                    const float vkp = Vm[k][p], vkq = Vm[k][q];
                    Vm[k][p] = c * vkp - s * vkq;
                    Vm[k][q] = s * vkp + c * vkq;
                }
            }
        }

        float wv[3] = {Bm[0][0], Bm[1][1], Bm[2][2]};
        int id[3] = {0, 1, 2};
        if (wv[id[0]] < wv[id[1]]) { int t = id[0]; id[0] = id[1]; id[1] = t; }
        if (wv[id[1]] < wv[id[2]]) { int t = id[1]; id[1] = id[2]; id[2] = t; }
        if (wv[id[0]] < wv[id[1]]) { int t = id[0]; id[0] = id[1]; id[1] = t; }

        float U[3][3], Vc[3][3], sv[3];
        #pragma unroll
        for (int i = 0; i < 3; i++) {
            const int j = id[i];
            const float v0 = Vm[0][j], v1 = Vm[1][j], v2 = Vm[2][j];
            const float u0 = A[0][0]*v0 + A[0][1]*v1 + A[0][2]*v2;
            const float u1 = A[1][0]*v0 + A[1][1]*v1 + A[1][2]*v2;
            const float u2 = A[2][0]*v0 + A[2][1]*v1 + A[2][2]*v2;
            const float nu = sqrtf(u0*u0 + u1*u1 + u2*u2);  // sigma_i
            sv[i] = nu;
            const float inv = (nu > 1e-30f) ? 1.0f / nu : 0.0f;
            U[0][i] = u0 * inv; U[1][i] = u1 * inv; U[2][i] = u2 * inv;
            Vc[0][i] = v0; Vc[1][i] = v1; Vc[2][i] = v2;
        }

        const float d3 = (detA < 0.0f) ? -1.0f : 1.0f;
        const float dd[3] = {1.0f, 1.0f, d3};
        const float scale = (sv[0] + sv[1] + d3 * sv[2]) / var_s;

        float* outp = g_params + b * 12;
        #pragma unroll
        for (int r = 0; r < 3; r++) {
            float row[3];
            #pragma unroll
            for (int c = 0; c < 3; c++) {
                float acc = 0.0f;
                #pragma unroll
                for (int i = 0; i < 3; i++) acc += dd[i] * U[r][i] * Vc[c][i];
                row[c] = scale * acc;
                outp[r * 3 + c] = row[c];
            }
            outp[9 + r] = ((r == 0) ? mud0 : (r == 1) ? mud1 : mud2)
                - (row[0] * mus0 + row[1] * mus1 + row[2] * mus2);
        }
    }
}

// ---------------------------------------------------------------------------
// Kernel 2: apply transform — one full wave (1184 blocks, 32 regs, 8/SM),
// contiguous-chunk partitioning: block bid owns units
// [bid*4096/1184, (bid+1)*4096/1184) -> each block streams a 3-4 MB
// contiguous region (better DRAM row/prefetch locality than the 77MB-stride
// grid-stride walk). Work imbalance identical (3 or 4 units per block).
// ---------------------------------------------------------------------------
__global__ void __launch_bounds__(256)
apply_kernel(const float4* __restrict__ Off,
             const float4* __restrict__ Mp,
             float4*       __restrict__ Out)
{
    const int tid = threadIdx.x;

    const int u_begin = (int)(((long long)blockIdx.x       * APPLY_UNITS) / APPLY_BLOCKS);
    const int u_end   = (int)(((long long)(blockIdx.x + 1) * APPLY_UNITS) / APPLY_BLOCKS);

    for (int u = u_begin; u < u_end; u++) {
        const int b = u >> 6;                    // 64 units per batch
        const int g = ((u & 63) << 8) + tid;     // group within batch image
        const int base = b * 3 * HW4 + g;

        // Front-batch the six wide loads (the DRAM-latency stream).
        const float4 o0 = Off[base];
        const float4 o1 = Off[base + HW4];
        const float4 o2 = Off[base + 2 * HW4];
        const float4 m0 = Mp[g];
        const float4 m1 = Mp[g + HW4];
        const float4 m2 = Mp[g + 2 * HW4];

        // L1-hit uniform param loads issued after the wide loads.
        const float* p = g_params + b * 12;
        const float p00 = p[0], p01 = p[1], p02 = p[2];
        const float p10 = p[3], p11 = p[4], p12 = p[5];
        const float p20 = p[6], p21 = p[7], p22 = p[8];
        const float t0  = p[9], t1  = p[10], t2 = p[11];

        float4 r0, r1, r2;

#define APPLY_LANE(j)                                                        \
        {                                                                    \
            const float x =  fmaf(o0.j, 4.0f, m0.j);                         \
            const float y = -fmaf(o1.j, 4.0f, m1.j);                         \
            const float z =  fmaf(o2.j, 4.0f, m2.j);                         \
            r0.j = fmaf(p00, x, fmaf(p01, y, fmaf(p02, z, t0)));             \
            r1.j = fmaf(p10, x, fmaf(p11, y, fmaf(p12, z, t1)));             \
            r2.j = fmaf(p20, x, fmaf(p21, y, fmaf(p22, z, t2)));             \
        }

        APPLY_LANE(x)
        APPLY_LANE(y)
        APPLY_LANE(z)
        APPLY_LANE(w)
#undef APPLY_LANE

        Out[base]           = r0;
        Out[base + HW4]     = r1;
        Out[base + 2 * HW4] = r2;
    }
}

// ---------------------------------------------------------------------------
extern "C" void kernel_launch(void* const* d_in, const int* in_sizes, int n_in,
                              void* d_out, int out_size)
{
    const float* Off = (const float*)d_in[0];   // [64,3,256,256]
    const float* Pos = (const float*)d_in[1];   // [64,3,256,256]
    const float* Mp  = (const float*)d_in[2];   // [3,256,256]
    const int*   uv  = (const int*)  d_in[3];   // [68,2]
    float*       Out = (float*)d_out;           // [64,3,256,256]

    estimate_kernel<<<BATCH, 128>>>(Off, Pos, Mp, uv);

    apply_kernel<<<APPLY_BLOCKS, 256>>>((const float4*)Off,
                                        (const float4*)Mp,
                                        (float4*)Out);
}

// round 16
// speedup vs baseline: 1.0340x; 1.0340x over previous
#include <cuda_runtime.h>
#include <math.h>

static constexpr int BATCH = 64;
static constexpr int H  = 256;
static constexpr int W  = 256;
static constexpr int HW = H * W;          // 65536
static constexpr int HW4 = HW / 4;        // 16384 float4 groups per channel
static constexpr int NK = 68;
static constexpr int APPLY_UNITS = BATCH * HW4 / 256;  // 4096 units
static constexpr int APPLY_BLOCKS = 1184;              // 148 SMs x 8 resident

// Per-batch similarity transform: 9 floats sR (row-major [d][c]) + 3 floats t.
__device__ float g_params[BATCH * 12];

// ---------------------------------------------------------------------------
// Kernel 1: per-batch Umeyama estimation (64 blocks x 128 threads).
// (Latency-floor version; measured invariant across rewrites.)
// ---------------------------------------------------------------------------
__global__ void __launch_bounds__(128)
estimate_kernel(const float* __restrict__ Off,
                const float* __restrict__ Pos,
                const float* __restrict__ Mp,
                const int*   __restrict__ uv)
{
    const int b   = blockIdx.x;
    const int tid = threadIdx.x;

    __shared__ float mom[16][NK + 1];
    __shared__ float ssum[16];

    if (tid < NK) {
        const int h = __ldg(&uv[2 * tid + 0]);
        const int w = __ldg(&uv[2 * tid + 1]);
        const int base = b * 3 * HW + h * W + w;
        const int mb   = h * W + w;
        // offsetmap = (Offset*4 + mean) * REVERT, REVERT = [1,-1,1]
        const float s0 =  fmaf(Off[base         ], 4.0f, Mp[mb         ]);
        const float s1 = -fmaf(Off[base +    HW ], 4.0f, Mp[mb +    HW ]);
        const float s2 =  fmaf(Off[base + 2*HW  ], 4.0f, Mp[mb + 2*HW  ]);
        const float d0 = Pos[base];
        const float d1 = Pos[base + HW];
        const float d2 = Pos[base + 2 * HW];

        mom[0][tid]  = s0;       mom[1][tid]  = s1;       mom[2][tid]  = s2;
        mom[3][tid]  = d0;       mom[4][tid]  = d1;       mom[5][tid]  = d2;
        mom[6][tid]  = d0 * s0;  mom[7][tid]  = d0 * s1;  mom[8][tid]  = d0 * s2;
        mom[9][tid]  = d1 * s0;  mom[10][tid] = d1 * s1;  mom[11][tid] = d1 * s2;
        mom[12][tid] = d2 * s0;  mom[13][tid] = d2 * s1;  mom[14][tid] = d2 * s2;
        mom[15][tid] = s0 * s0 + s1 * s1 + s2 * s2;
    }
    __syncthreads();

    if (tid < 16) {
        float a0 = 0.f, a1 = 0.f, a2 = 0.f, a3 = 0.f;
        #pragma unroll
        for (int i = 0; i < 68; i += 4) {
            a0 += mom[tid][i + 0];
            a1 += mom[tid][i + 1];
            a2 += mom[tid][i + 2];
            a3 += mom[tid][i + 3];
        }
        ssum[tid] = ((a0 + a1) + (a2 + a3)) * (1.0f / NK);
    }
    __syncthreads();

    if (tid == 0) {
        const float mus0 = ssum[0], mus1 = ssum[1], mus2 = ssum[2];
        const float mud0 = ssum[3], mud1 = ssum[4], mud2 = ssum[5];

        float A[3][3];
        A[0][0] = ssum[6]  - mud0*mus0; A[0][1] = ssum[7]  - mud0*mus1; A[0][2] = ssum[8]  - mud0*mus2;
        A[1][0] = ssum[9]  - mud1*mus0; A[1][1] = ssum[10] - mud1*mus1; A[1][2] = ssum[11] - mud1*mus2;
        A[2][0] = ssum[12] - mud2*mus0; A[2][1] = ssum[13] - mud2*mus1; A[2][2] = ssum[14] - mud2*mus2;
        const float var_s = ssum[15] - (mus0*mus0 + mus1*mus1 + mus2*mus2);

        const float detA =
              A[0][0] * (A[1][1]*A[2][2] - A[1][2]*A[2][1])
            - A[0][1] * (A[1][0]*A[2][2] - A[1][2]*A[2][0])
            + A[0][2] * (A[1][0]*A[2][1] - A[1][1]*A[2][0]);

        float Bm[3][3], Vm[3][3] = {{1,0,0},{0,1,0},{0,0,1}};
        #pragma unroll
        for (int i = 0; i < 3; i++)
            #pragma unroll
            for (int j = 0; j < 3; j++) {
                float acc = 0.0f;
                #pragma unroll
                for (int k = 0; k < 3; k++) acc += A[k][i] * A[k][j];
                Bm[i][j] = acc;
            }

        const int PP[3] = {0, 0, 1}, QQ[3] = {1, 2, 2};
        #pragma unroll 1
        for (int sweep = 0; sweep < 4; sweep++) {
            #pragma unroll
            for (int r = 0; r < 3; r++) {
                const int p = PP[r], q = QQ[r];
                const float apq = Bm[p][q];
                if (fabsf(apq) < 1e-30f) continue;
                const float theta = (Bm[q][q] - Bm[p][p]) / (2.0f * apq);
                const float tt = ((theta >= 0.0f) ? 1.0f : -1.0f) /
                                 (fabsf(theta) + sqrtf(theta * theta + 1.0f));
                const float c = rsqrtf(tt * tt + 1.0f);
                const float s = tt * c;
                #pragma unroll
                for (int k = 0; k < 3; k++) {
                    const float bkp = Bm[k][p], bkq = Bm[k][q];
                    Bm[k][p] = c * bkp - s * bkq;
                    Bm[k][q] = s * bkp + c * bkq;
                }
                #pragma unroll
                for (int k = 0; k < 3; k++) {
                    const float bpk = Bm[p][k], bqk = Bm[q][k];
                    Bm[p][k] = c * bpk - s * bqk;
                    Bm[q][k] = s * bpk + c * bqk;
                }
                #pragma unroll
                for (int k = 0; k < 3; k++) {
                    const float vkp = Vm[k][p], vkq = Vm[k][q];
                    Vm[k][p] = c * vkp - s * vkq;
                    Vm[k][q] = s * vkp + c * vkq;
                }
            }
        }

        float wv[3] = {Bm[0][0], Bm[1][1], Bm[2][2]};
        int id[3] = {0, 1, 2};
        if (wv[id[0]] < wv[id[1]]) { int t = id[0]; id[0] = id[1]; id[1] = t; }
        if (wv[id[1]] < wv[id[2]]) { int t = id[1]; id[1] = id[2]; id[2] = t; }
        if (wv[id[0]] < wv[id[1]]) { int t = id[0]; id[0] = id[1]; id[1] = t; }

        float U[3][3], Vc[3][3], sv[3];
        #pragma unroll
        for (int i = 0; i < 3; i++) {
            const int j = id[i];
            const float v0 = Vm[0][j], v1 = Vm[1][j], v2 = Vm[2][j];
            const float u0 = A[0][0]*v0 + A[0][1]*v1 + A[0][2]*v2;
            const float u1 = A[1][0]*v0 + A[1][1]*v1 + A[1][2]*v2;
            const float u2 = A[2][0]*v0 + A[2][1]*v1 + A[2][2]*v2;
            const float nu = sqrtf(u0*u0 + u1*u1 + u2*u2);  // sigma_i
            sv[i] = nu;
            const float inv = (nu > 1e-30f) ? 1.0f / nu : 0.0f;
            U[0][i] = u0 * inv; U[1][i] = u1 * inv; U[2][i] = u2 * inv;
            Vc[0][i] = v0; Vc[1][i] = v1; Vc[2][i] = v2;
        }

        const float d3 = (detA < 0.0f) ? -1.0f : 1.0f;
        const float dd[3] = {1.0f, 1.0f, d3};
        const float scale = (sv[0] + sv[1] + d3 * sv[2]) / var_s;

        float* outp = g_params + b * 12;
        #pragma unroll
        for (int r = 0; r < 3; r++) {
            float row[3];
            #pragma unroll
            for (int c = 0; c < 3; c++) {
                float acc = 0.0f;
                #pragma unroll
                for (int i = 0; i < 3; i++) acc += dd[i] * U[r][i] * Vc[c][i];
                row[c] = scale * acc;
                outp[r * 3 + c] = row[c];
            }
            outp[9 + r] = ((r == 0) ? mud0 : (r == 1) ? mud1 : mud2)
                - (row[0] * mus0 + row[1] * mus1 + row[2] * mus2);
        }
    }
}

// ---------------------------------------------------------------------------
// Kernel 2: apply transform — one-wave grid-stride (1184 blocks, 32 regs,
// 8 blocks/SM). The stride-1184 interleave spreads concurrent traffic
// uniformly over L2 slices/HBM channels (measured +11% BW vs contiguous
// chunks) and eliminates the 46%-empty tail wave of a 4096-block launch.
// ---------------------------------------------------------------------------
__global__ void __launch_bounds__(256)
apply_kernel(const float4* __restrict__ Off,
             const float4* __restrict__ Mp,
             float4*       __restrict__ Out)
{
    const int tid = threadIdx.x;

    for (int u = blockIdx.x; u < APPLY_UNITS; u += APPLY_BLOCKS) {
        const int b = u >> 6;                    // 64 units per batch
        const int g = ((u & 63) << 8) + tid;     // group within batch image
        const int base = b * 3 * HW4 + g;

        // Front-batch the six wide loads (the DRAM-latency stream).
        const float4 o0 = Off[base];
        const float4 o1 = Off[base + HW4];
        const float4 o2 = Off[base + 2 * HW4];
        const float4 m0 = Mp[g];
        const float4 m1 = Mp[g + HW4];
        const float4 m2 = Mp[g + 2 * HW4];

        // L1-hit uniform param loads issued after the wide loads.
        const float* p = g_params + b * 12;
        const float p00 = p[0], p01 = p[1], p02 = p[2];
        const float p10 = p[3], p11 = p[4], p12 = p[5];
        const float p20 = p[6], p21 = p[7], p22 = p[8];
        const float t0  = p[9], t1  = p[10], t2 = p[11];

        float4 r0, r1, r2;

#define APPLY_LANE(j)                                                        \
        {                                                                    \
            const float x =  fmaf(o0.j, 4.0f, m0.j);                         \
            const float y = -fmaf(o1.j, 4.0f, m1.j);                         \
            const float z =  fmaf(o2.j, 4.0f, m2.j);                         \
            r0.j = fmaf(p00, x, fmaf(p01, y, fmaf(p02, z, t0)));             \
            r1.j = fmaf(p10, x, fmaf(p11, y, fmaf(p12, z, t1)));             \
            r2.j = fmaf(p20, x, fmaf(p21, y, fmaf(p22, z, t2)));             \
        }

        APPLY_LANE(x)
        APPLY_LANE(y)
        APPLY_LANE(z)
        APPLY_LANE(w)
#undef APPLY_LANE

        Out[base]           = r0;
        Out[base + HW4]     = r1;
        Out[base + 2 * HW4] = r2;
    }
}

// ---------------------------------------------------------------------------
extern "C" void kernel_launch(void* const* d_in, const int* in_sizes, int n_in,
                              void* d_out, int out_size)
{
    const float* Off = (const float*)d_in[0];   // [64,3,256,256]
    const float* Pos = (const float*)d_in[1];   // [64,3,256,256]
    const float* Mp  = (const float*)d_in[2];   // [3,256,256]
    const int*   uv  = (const int*)  d_in[3];   // [68,2]
    float*       Out = (float*)d_out;           // [64,3,256,256]

    estimate_kernel<<<BATCH, 128>>>(Off, Pos, Mp, uv);

    apply_kernel<<<APPLY_BLOCKS, 256>>>((const float4*)Off,
                                        (const float4*)Mp,
                                        (float4*)Out);
}